// round 16
// baseline (speedup 1.0000x reference)
#include <cuda_runtime.h>
#include <cuda_fp16.h>
#include <math.h>
#include <stdint.h>

#define NB   4
#define NS   2048
#define ND   1024
#define NH   16
#define NDK  64
#define NM   (NB*NS)          // 8192 rows

// 0.125 * log2(e): folded into Q projection so softmax uses ex2.approx
#define QSCALE 0.1803368801111204f

// ---------------- scratch (no allocations allowed) ----------------
__device__ __align__(256) __half g_abuf[(size_t)3*NM*ND]; // Q|K|V fp16 acts
__device__ __align__(256) __half g_wbuf[(size_t)4*ND*ND]; // Wq|Wk|Wv|Wo fp16
__device__ __align__(256) __half g_qh[NB*NH*NS*NDK];      // [B,H,S,Dk] (scaled)
__device__ __align__(256) __half g_kh[NB*NH*NS*NDK];
__device__ __align__(256) __half g_vth[NB*NH*NDK*NS];     // [B,H,Dk,S]

// ============================================================================
// PTX helpers
// ============================================================================
__device__ __forceinline__ uint32_t smem_u32(const void* p) {
    uint32_t a;
    asm("{ .reg .u64 t; cvta.to.shared.u64 t, %1; cvt.u32.u64 %0, t; }"
        : "=r"(a) : "l"(p));
    return a;
}
__device__ __forceinline__ void cp_async16(uint32_t dst, const void* src) {
    asm volatile("cp.async.cg.shared.global [%0], [%1], 16;"
                 :: "r"(dst), "l"(src) : "memory");
}
__device__ __forceinline__ void cp_commit() {
    asm volatile("cp.async.commit_group;" ::: "memory");
}
__device__ __forceinline__ void cp_wait_all() {
    asm volatile("cp.async.wait_group 0;" ::: "memory");
}
__device__ __forceinline__ void ldm_x4(uint32_t* r, uint32_t addr) {
    asm volatile("ldmatrix.sync.aligned.m8n8.x4.shared.b16 {%0,%1,%2,%3}, [%4];"
                 : "=r"(r[0]), "=r"(r[1]), "=r"(r[2]), "=r"(r[3]) : "r"(addr));
}
__device__ __forceinline__ void mma_f16(float* d, const uint32_t* a,
                                        const uint32_t* b) {
    asm volatile(
        "mma.sync.aligned.m16n8k16.row.col.f32.f16.f16.f32 "
        "{%0,%1,%2,%3}, {%4,%5,%6,%7}, {%8,%9}, {%0,%1,%2,%3};"
        : "+f"(d[0]), "+f"(d[1]), "+f"(d[2]), "+f"(d[3])
        : "r"(a[0]), "r"(a[1]), "r"(a[2]), "r"(a[3]), "r"(b[0]), "r"(b[1]));
}
__device__ __forceinline__ uint32_t f22h2(float x, float y) {
    __half2 h = __float22half2_rn(make_float2(x, y));
    return *(uint32_t*)&h;
}
__device__ __forceinline__ uint32_t ex2h2(uint32_t x) {
    uint32_t y;
    asm("ex2.approx.f16x2 %0, %1;" : "=r"(y) : "r"(x));
    return y;
}

// ============================================================================
// merged convert fp32 -> fp16 (activations + weights in one launch)
// ============================================================================
#define ACT_BLKS (3*(NM*ND/4/256))   // 24576
#define W_BLKS   (4*(ND*ND/4/256))   // 4096

__global__ void __launch_bounds__(256) conv_kernel(
    const float* __restrict__ Q, const float* __restrict__ K,
    const float* __restrict__ V,
    const float* __restrict__ Wq, const float* __restrict__ Wk,
    const float* __restrict__ Wv, const float* __restrict__ Wo,
    __half* __restrict__ Ya, __half* __restrict__ Yw)
{
    const int bid = blockIdx.x;
    const float* X;
    __half* Y;
    int i;
    if (bid < ACT_BLKS) {
        const int z = bid / (NM*ND/4/256);
        const int r = bid % (NM*ND/4/256);
        X = (z == 0) ? Q : (z == 1) ? K : V;
        Y = Ya + (size_t)z * NM * ND;
        i = r * 256 + threadIdx.x;
    } else {
        const int b2 = bid - ACT_BLKS;
        const int z = b2 / (ND*ND/4/256);
        const int r = b2 % (ND*ND/4/256);
        X = (z == 0) ? Wq : (z == 1) ? Wk : (z == 2) ? Wv : Wo;
        Y = Yw + (size_t)z * ND * ND;
        i = r * 256 + threadIdx.x;
    }
    float4 x = *(const float4*)(X + (size_t)i * 4);
    uint2 h;
    h.x = f22h2(x.x, x.y);
    h.y = f22h2(x.z, x.w);
    *(uint2*)(Y + (size_t)i * 4) = h;
}

// ============================================================================
// GEMM core
// ============================================================================
#define LDT       144
#define ATILE     (128*LDT)
#define SMEM_GEMM (4*ATILE)
#define NCH       (ND/64)                    // 16

__device__ __forceinline__ void gemm_mainloop(
    const __half* __restrict__ A, const __half* __restrict__ W,
    char* smem, int tid, int bm, int bn, float acc[4][4][4])
{
    const uint32_t sA = smem_u32(smem);
    const uint32_t sB = sA + 2*ATILE;
    const int lane = tid & 31;
    const int wid  = tid >> 5;
    const int wm   = wid >> 2;
    const int wn   = wid & 3;

    const int lr  = tid >> 3;
    const int lc  = tid & 7;
    const __half* Ag = A + (size_t)(bm + lr) * ND + lc * 8;
    const __half* Wg = W + (size_t)(bn + lr) * ND + lc * 8;
    const uint32_t dstOff = (uint32_t)lr * LDT + (uint32_t)lc * 16;

    const uint32_t lrow = lane & 15;
    const uint32_t lk   = (lane >> 4) * 16;
    const uint32_t aBase = sA + (wm*64 + lrow) * LDT + lk;
    const uint32_t bBase = sB + (wn*32 + lrow) * LDT + lk;

    #pragma unroll
    for (int mt = 0; mt < 4; ++mt)
        #pragma unroll
        for (int nt = 0; nt < 4; ++nt)
            #pragma unroll
            for (int j = 0; j < 4; ++j) acc[mt][nt][j] = 0.f;

    #pragma unroll
    for (int p = 0; p < 4; ++p) {
        cp_async16(sA + dstOff + p*32*LDT, Ag + (size_t)p*32*ND);
        cp_async16(sB + dstOff + p*32*LDT, Wg + (size_t)p*32*ND);
    }
    cp_commit();

    for (int c = 0; c < NCH; ++c) {
        cp_wait_all();
        __syncthreads();

        if (c + 1 < NCH) {
            const uint32_t nb = (uint32_t)((c + 1) & 1) * ATILE;
            const size_t   ko = (size_t)(c + 1) * 64;
            #pragma unroll
            for (int p = 0; p < 4; ++p) {
                cp_async16(sA + nb + dstOff + p*32*LDT, Ag + (size_t)p*32*ND + ko);
                cp_async16(sB + nb + dstOff + p*32*LDT, Wg + (size_t)p*32*ND + ko);
            }
            cp_commit();
        }

        const uint32_t bo = (uint32_t)(c & 1) * ATILE;
        const uint32_t aAddr = aBase + bo;
        const uint32_t bAddr = bBase + bo;

        #pragma unroll
        for (int ks = 0; ks < 4; ++ks) {
            uint32_t af[4][4];
            #pragma unroll
            for (int mt = 0; mt < 4; ++mt)
                ldm_x4(af[mt], aAddr + mt*16*LDT + ks*32);

            uint32_t bf[4][2];
            {
                uint32_t r[4];
                ldm_x4(r, bAddr + ks*32);
                bf[0][0] = r[0]; bf[0][1] = r[2];
                bf[1][0] = r[1]; bf[1][1] = r[3];
                ldm_x4(r, bAddr + 16*LDT + ks*32);
                bf[2][0] = r[0]; bf[2][1] = r[2];
                bf[3][0] = r[1]; bf[3][1] = r[3];
            }
            #pragma unroll
            for (int mt = 0; mt < 4; ++mt)
                #pragma unroll
                for (int nt = 0; nt < 4; ++nt)
                    mma_f16(acc[mt][nt], af[mt], bf[nt]);
        }
    }
}

// ---- batched QKV projection
__global__ void __launch_bounds__(256, 2) qkv_gemm_kernel(
    const __half* __restrict__ AB, const __half* __restrict__ WB,
    const float* __restrict__ bq, const float* __restrict__ bk,
    const float* __restrict__ bv,
    __half* __restrict__ qh, __half* __restrict__ kh, __half* __restrict__ vth)
{
    extern __shared__ char smem[];
    const int z   = blockIdx.z;
    const int tid = threadIdx.x;
    const int bm  = blockIdx.y * 128;
    const int bn  = blockIdx.x * 128;

    const __half* A = AB + (size_t)z * NM * ND;
    const __half* W = WB + (size_t)z * ND * ND;
    const float* bias = (z == 0) ? bq : (z == 1) ? bk : bv;
    const float scale = (z == 0) ? QSCALE : 1.0f;

    float acc[4][4][4];
    gemm_mainloop(A, W, smem, tid, bm, bn, acc);

    const int lane = tid & 31;
    const int wid  = tid >> 5;
    const int wm   = wid >> 2;
    const int wn   = wid & 3;
    const int g  = lane >> 2;
    const int cj = (lane & 3) * 2;
    #pragma unroll
    for (int mt = 0; mt < 4; ++mt) {
        #pragma unroll
        for (int nt = 0; nt < 4; ++nt) {
            const int n  = bn + wn*32 + nt*8 + cj;
            const float bx = bias[n], by = bias[n+1];
            #pragma unroll
            for (int half_ = 0; half_ < 2; ++half_) {
                const int m = bm + wm*64 + mt*16 + g + half_*8;
                const float vx = (acc[mt][nt][half_*2+0] + bx) * scale;
                const float vy = (acc[mt][nt][half_*2+1] + by) * scale;
                const int b_ = m >> 11, s_ = m & (NS-1);
                const int h_ = n >> 6,  d_ = n & 63;
                if (z < 2) {
                    __half* OH = (z == 0) ? qh : kh;
                    const size_t idx = ((size_t)(b_*NH + h_) << 17) + ((size_t)s_ << 6) + d_;
                    *(uint32_t*)&OH[idx] = f22h2(vx, vy);
                } else {
                    const size_t idx = ((size_t)(b_*NH + h_) << 17) + ((size_t)d_ << 11) + s_;
                    vth[idx] = __float2half_rn(vx);
                    vth[idx + 2048] = __float2half_rn(vy);
                }
            }
        }
    }
}

// ---- O projection: fp32 output
__global__ void __launch_bounds__(256, 2) oproj_gemm_kernel(
    const __half* __restrict__ A, const __half* __restrict__ W,
    const float* __restrict__ bias, float* __restrict__ C)
{
    extern __shared__ char smem[];
    const int tid = threadIdx.x;
    const int bm  = blockIdx.y * 128;
    const int bn  = blockIdx.x * 128;

    float acc[4][4][4];
    gemm_mainloop(A, W, smem, tid, bm, bn, acc);

    const int lane = tid & 31;
    const int wid  = tid >> 5;
    const int wm   = wid >> 2;
    const int wn   = wid & 3;
    const int g  = lane >> 2;
    const int cj = (lane & 3) * 2;
    #pragma unroll
    for (int mt = 0; mt < 4; ++mt) {
        #pragma unroll
        for (int nt = 0; nt < 4; ++nt) {
            const int n  = bn + wn*32 + nt*8 + cj;
            const float bx = bias[n], by = bias[n+1];
            #pragma unroll
            for (int half_ = 0; half_ < 2; ++half_) {
                const int m = bm + wm*64 + mt*16 + g + half_*8;
                float2 v;
                v.x = acc[mt][nt][half_*2+0] + bx;
                v.y = acc[mt][nt][half_*2+1] + by;
                *(float2*)&C[(size_t)m * ND + n] = v;
            }
        }
    }
}

// ============================================================================
// flash attention. CTA: 128 q-rows, 8 warps, occ 2.
// MUFU halved via ex2.approx.f16x2 (scores cvt'd to fp16 first — needed for
// the PV mma anyway). Row-sum l computed exactly by a ones-column mma
// (tensor pipe), removing all softmax FADDs and shuffle reductions.
// ============================================================================
#define QT  128
#define SST (QT*LDT)              // 18432 (Q region)
#define OKH 0
#define OVH (64*LDT)              // 9216
#define STG (2*64*LDT)            // 18432 per stage
#define SMEM_ATTN (SST + 2*STG)   // 55296

__device__ __forceinline__ void attn_load_stage(
    uint32_t s0, int t, int tid, size_t base,
    const __half* Kh, const __half* Vh)
{
    #pragma unroll
    for (int p = 0; p < 2; ++p) {
        const int idx = tid + p*256;
        const int row = idx >> 3;
        const int c   = idx & 7;
        const size_t gk = base + (size_t)(t*64 + row)*64 + c*8;
        const size_t gv = base + (size_t)row*2048 + (size_t)t*64 + c*8;
        const uint32_t d = (uint32_t)row*LDT + (uint32_t)c*16;
        cp_async16(s0 + OKH + d, Kh + gk);
        cp_async16(s0 + OVH + d, Vh + gv);
    }
}

__global__ void __launch_bounds__(256, 2) attn_mma_kernel(
    const __half* __restrict__ Qh,
    const __half* __restrict__ Kh, const __half* __restrict__ Vh,
    __half* __restrict__ O)
{
    extern __shared__ char smem[];
    const uint32_t sb = smem_u32(smem);
    const int tid  = threadIdx.x;
    const int lane = tid & 31;
    const int w    = tid >> 5;
    const int hh   = blockIdx.y, bb = blockIdx.z;
    const int q0   = blockIdx.x * QT;
    const size_t base = ((size_t)(bb*NH + hh)) << 17;

    {
        #pragma unroll
        for (int p = 0; p < 4; ++p) {
            const int idx = tid + p*256;
            const int row = idx >> 3;
            const int c   = idx & 7;
            const size_t gq = base + (size_t)(q0 + row)*64 + c*8;
            cp_async16(sb + (uint32_t)row*LDT + (uint32_t)c*16, Qh + gq);
        }
    }
    attn_load_stage(sb + SST, 0, tid, base, Kh, Vh);
    cp_commit();

    float o[8][4];
    #pragma unroll
    for (int nt = 0; nt < 8; ++nt)
        #pragma unroll
        for (int j = 0; j < 4; ++j) o[nt][j] = 0.f;
    float lacc[4] = {0.f, 0.f, 0.f, 0.f};      // ones-column mma accumulator

    const uint32_t ONES2 = 0x3C003C00u;         // fp16x2 {1.0, 1.0}
    const uint32_t bones[2] = {ONES2, ONES2};

    const uint32_t lrm = lane & 15;
    const uint32_t lkb = (lane >> 4) * 16;
    const uint32_t aH = sb + (w*16 + lrm)*LDT + lkb;

    for (int t = 0; t < NS/64; ++t) {
        cp_wait_all();
        __syncthreads();
        if (t + 1 < NS/64) {
            attn_load_stage(sb + SST + ((t+1)&1)*STG, t+1, tid, base, Kh, Vh);
            cp_commit();
        }

        const uint32_t st = sb + SST + (t&1)*STG;
        const uint32_t bK = st + OKH + lrm*LDT + lkb;
        const uint32_t bV = st + OVH + lrm*LDT + lkb;

        // ---- S2 = Qh . Kh^T (log2-domain scores)
        float s[8][4];
        #pragma unroll
        for (int nt = 0; nt < 8; ++nt)
            #pragma unroll
            for (int j = 0; j < 4; ++j) s[nt][j] = 0.f;

        #pragma unroll
        for (int ks = 0; ks < 4; ++ks) {
            uint32_t ah[4], bf[8][2];
            ldm_x4(ah, aH + ks*32);
            #pragma unroll
            for (int pr = 0; pr < 4; ++pr) {
                uint32_t r[4];
                ldm_x4(r, bK + pr*16*LDT + ks*32);
                bf[2*pr][0]   = r[0]; bf[2*pr][1]   = r[2];
                bf[2*pr+1][0] = r[1]; bf[2*pr+1][1] = r[3];
            }
            #pragma unroll
            for (int nt = 0; nt < 8; ++nt)
                mma_f16(s[nt], ah, bf[nt]);
        }

        // ---- P = 2^s: cvt score pairs to fp16x2, then one f16x2 ex2 each
        uint32_t ph[4][4];
        #pragma unroll
        for (int rh = 0; rh < 2; ++rh) {
            #pragma unroll
            for (int nt = 0; nt < 8; ++nt) {
                ph[nt>>1][(nt&1)*2 + rh] =
                    ex2h2(f22h2(s[nt][2*rh], s[nt][2*rh+1]));
            }
        }

        // ---- O += Ph . Vh ; l += Ph . ones (tensor-pipe row sums)
        #pragma unroll
        for (int ks = 0; ks < 4; ++ks) {
            uint32_t bv[8][2];
            #pragma unroll
            for (int pr = 0; pr < 4; ++pr) {
                uint32_t r[4];
                ldm_x4(r, bV + pr*16*LDT + ks*32);
                bv[2*pr][0]   = r[0]; bv[2*pr][1]   = r[2];
                bv[2*pr+1][0] = r[1]; bv[2*pr+1][1] = r[3];
            }
            #pragma unroll
            for (int nt = 0; nt < 8; ++nt)
                mma_f16(o[nt], ph[ks], bv[nt]);
            mma_f16(lacc, ph[ks], bones);
        }
    }

    // ---- epilogue: normalize (l exact per-row from ones-mma), write fp16
    const int g  = lane >> 2;
    const int cq = (lane & 3) * 2;
    #pragma unroll
    for (int rh = 0; rh < 2; ++rh) {
        const float inv = 1.f / lacc[2*rh];    // c0 = row g, c2 = row g+8
        const int qrow = q0 + w*16 + g + rh*8;
        __half* Orow = O + ((size_t)bb*NS + qrow) * ND;
        #pragma unroll
        for (int nt = 0; nt < 8; ++nt) {
            const float vx = o[nt][2*rh]   * inv;
            const float vy = o[nt][2*rh+1] * inv;
            const int colD = hh*64 + nt*8 + cq;
            *(uint32_t*)&Orow[colD] = f22h2(vx, vy);
        }
    }
}

// ---------------- launch ----------------
extern "C" void kernel_launch(void* const* d_in, const int* in_sizes, int n_in,
                              void* d_out, int out_size)
{
    const float* Q  = (const float*)d_in[0];
    const float* K  = (const float*)d_in[1];
    const float* V  = (const float*)d_in[2];
    const float* Wq = (const float*)d_in[3];
    const float* bq = (const float*)d_in[4];
    const float* Wk = (const float*)d_in[5];
    const float* bk = (const float*)d_in[6];
    const float* Wv = (const float*)d_in[7];
    const float* bv = (const float*)d_in[8];
    const float* Wo = (const float*)d_in[9];
    const float* bo = (const float*)d_in[10];
    float* out = (float*)d_out;

    void *pab, *pwb, *pqh, *pkh, *pvh;
    cudaGetSymbolAddress(&pab, g_abuf);
    cudaGetSymbolAddress(&pwb, g_wbuf);
    cudaGetSymbolAddress(&pqh, g_qh);
    cudaGetSymbolAddress(&pkh, g_kh);
    cudaGetSymbolAddress(&pvh, g_vth);
    __half* ab = (__half*)pab;
    __half* wb = (__half*)pwb;

    cudaFuncSetAttribute((const void*)qkv_gemm_kernel,
                         cudaFuncAttributeMaxDynamicSharedMemorySize, SMEM_GEMM);
    cudaFuncSetAttribute((const void*)oproj_gemm_kernel,
                         cudaFuncAttributeMaxDynamicSharedMemorySize, SMEM_GEMM);
    cudaFuncSetAttribute((const void*)attn_mma_kernel,
                         cudaFuncAttributeMaxDynamicSharedMemorySize, SMEM_ATTN);

    // 1) merged converts (activations + weights, one launch)
    conv_kernel<<<ACT_BLKS + W_BLKS, 256>>>(Q, K, V, Wq, Wk, Wv, Wo, ab, wb);

    // 2) batched QKV projections (Q scaled by 0.125*log2e)
    qkv_gemm_kernel<<<dim3(ND/128, NM/128, 3), 256, SMEM_GEMM>>>(
        ab, wb, bq, bk, bv,
        (__half*)pqh, (__half*)pkh, (__half*)pvh);

    // 3) attention -> fp16 activations into g_abuf section 0
    attn_mma_kernel<<<dim3(NS/QT, NH, NB), 256, SMEM_ATTN>>>(
        (const __half*)pqh, (const __half*)pkh, (const __half*)pvh, ab);

    // 4) output projection (Wo is section 3 of g_wbuf)
    oproj_gemm_kernel<<<dim3(ND/128, NM/128), 256, SMEM_GEMM>>>(
        ab, wb + (size_t)3*ND*ND, bo, out);
}

// round 17
// speedup vs baseline: 1.5095x; 1.5095x over previous
#include <cuda_runtime.h>
#include <cuda_fp16.h>
#include <math.h>
#include <stdint.h>

#define NB   4
#define NS   2048
#define ND   1024
#define NH   16
#define NDK  64
#define NM   (NB*NS)          // 8192 rows

// 0.125 * log2(e): folded into Q projection so softmax uses ex2.approx
#define QSCALE 0.1803368801111204f

// ---------------- scratch (no allocations allowed) ----------------
__device__ __align__(256) __half g_abuf[(size_t)3*NM*ND]; // Q|K|V fp16 acts
__device__ __align__(256) __half g_wbuf[(size_t)4*ND*ND]; // Wq|Wk|Wv|Wo fp16
__device__ __align__(256) __half g_qh[NB*NH*NS*NDK];      // [B,H,S,Dk] (scaled)
__device__ __align__(256) __half g_kh[NB*NH*NS*NDK];
__device__ __align__(256) __half g_vth[NB*NH*NDK*NS];     // [B,H,Dk,S]

// ============================================================================
// PTX helpers
// ============================================================================
__device__ __forceinline__ uint32_t smem_u32(const void* p) {
    uint32_t a;
    asm("{ .reg .u64 t; cvta.to.shared.u64 t, %1; cvt.u32.u64 %0, t; }"
        : "=r"(a) : "l"(p));
    return a;
}
__device__ __forceinline__ void cp_async16(uint32_t dst, const void* src) {
    asm volatile("cp.async.cg.shared.global [%0], [%1], 16;"
                 :: "r"(dst), "l"(src) : "memory");
}
__device__ __forceinline__ void cp_commit() {
    asm volatile("cp.async.commit_group;" ::: "memory");
}
__device__ __forceinline__ void cp_wait_all() {
    asm volatile("cp.async.wait_group 0;" ::: "memory");
}
__device__ __forceinline__ void cp_wait_1() {
    asm volatile("cp.async.wait_group 1;" ::: "memory");
}
__device__ __forceinline__ void ldm_x4(uint32_t* r, uint32_t addr) {
    asm volatile("ldmatrix.sync.aligned.m8n8.x4.shared.b16 {%0,%1,%2,%3}, [%4];"
                 : "=r"(r[0]), "=r"(r[1]), "=r"(r[2]), "=r"(r[3]) : "r"(addr));
}
__device__ __forceinline__ void mma_f16(float* d, const uint32_t* a,
                                        const uint32_t* b) {
    asm volatile(
        "mma.sync.aligned.m16n8k16.row.col.f32.f16.f16.f32 "
        "{%0,%1,%2,%3}, {%4,%5,%6,%7}, {%8,%9}, {%0,%1,%2,%3};"
        : "+f"(d[0]), "+f"(d[1]), "+f"(d[2]), "+f"(d[3])
        : "r"(a[0]), "r"(a[1]), "r"(a[2]), "r"(a[3]), "r"(b[0]), "r"(b[1]));
}
__device__ __forceinline__ uint32_t f22h2(float x, float y) {
    __half2 h = __float22half2_rn(make_float2(x, y));
    return *(uint32_t*)&h;
}
__device__ __forceinline__ float ex2f(float x) {
    float y;
    asm("ex2.approx.f32 %0, %1;" : "=f"(y) : "f"(x));
    return y;
}

// ============================================================================
// merged convert fp32 -> fp16 (activations + weights in one launch)
// ============================================================================
#define ACT_BLKS (3*(NM*ND/4/256))   // 24576
#define W_BLKS   (4*(ND*ND/4/256))   // 4096

__global__ void __launch_bounds__(256) conv_kernel(
    const float* __restrict__ Q, const float* __restrict__ K,
    const float* __restrict__ V,
    const float* __restrict__ Wq, const float* __restrict__ Wk,
    const float* __restrict__ Wv, const float* __restrict__ Wo,
    __half* __restrict__ Ya, __half* __restrict__ Yw)
{
    const int bid = blockIdx.x;
    const float* X;
    __half* Y;
    int i;
    if (bid < ACT_BLKS) {
        const int z = bid / (NM*ND/4/256);
        const int r = bid % (NM*ND/4/256);
        X = (z == 0) ? Q : (z == 1) ? K : V;
        Y = Ya + (size_t)z * NM * ND;
        i = r * 256 + threadIdx.x;
    } else {
        const int b2 = bid - ACT_BLKS;
        const int z = b2 / (ND*ND/4/256);
        const int r = b2 % (ND*ND/4/256);
        X = (z == 0) ? Wq : (z == 1) ? Wk : (z == 2) ? Wv : Wo;
        Y = Yw + (size_t)z * ND * ND;
        i = r * 256 + threadIdx.x;
    }
    float4 x = *(const float4*)(X + (size_t)i * 4);
    uint2 h;
    h.x = f22h2(x.x, x.y);
    h.y = f22h2(x.z, x.w);
    *(uint2*)(Y + (size_t)i * 4) = h;
}

// ============================================================================
// GEMM core
// ============================================================================
#define LDT       144
#define ATILE     (128*LDT)
#define SMEM_GEMM (4*ATILE)
#define NCH       (ND/64)                    // 16

__device__ __forceinline__ void gemm_mainloop(
    const __half* __restrict__ A, const __half* __restrict__ W,
    char* smem, int tid, int bm, int bn, float acc[4][4][4])
{
    const uint32_t sA = smem_u32(smem);
    const uint32_t sB = sA + 2*ATILE;
    const int lane = tid & 31;
    const int wid  = tid >> 5;
    const int wm   = wid >> 2;
    const int wn   = wid & 3;

    const int lr  = tid >> 3;
    const int lc  = tid & 7;
    const __half* Ag = A + (size_t)(bm + lr) * ND + lc * 8;
    const __half* Wg = W + (size_t)(bn + lr) * ND + lc * 8;
    const uint32_t dstOff = (uint32_t)lr * LDT + (uint32_t)lc * 16;

    const uint32_t lrow = lane & 15;
    const uint32_t lk   = (lane >> 4) * 16;
    const uint32_t aBase = sA + (wm*64 + lrow) * LDT + lk;
    const uint32_t bBase = sB + (wn*32 + lrow) * LDT + lk;

    #pragma unroll
    for (int mt = 0; mt < 4; ++mt)
        #pragma unroll
        for (int nt = 0; nt < 4; ++nt)
            #pragma unroll
            for (int j = 0; j < 4; ++j) acc[mt][nt][j] = 0.f;

    #pragma unroll
    for (int p = 0; p < 4; ++p) {
        cp_async16(sA + dstOff + p*32*LDT, Ag + (size_t)p*32*ND);
        cp_async16(sB + dstOff + p*32*LDT, Wg + (size_t)p*32*ND);
    }
    cp_commit();

    for (int c = 0; c < NCH; ++c) {
        cp_wait_all();
        __syncthreads();

        if (c + 1 < NCH) {
            const uint32_t nb = (uint32_t)((c + 1) & 1) * ATILE;
            const size_t   ko = (size_t)(c + 1) * 64;
            #pragma unroll
            for (int p = 0; p < 4; ++p) {
                cp_async16(sA + nb + dstOff + p*32*LDT, Ag + (size_t)p*32*ND + ko);
                cp_async16(sB + nb + dstOff + p*32*LDT, Wg + (size_t)p*32*ND + ko);
            }
            cp_commit();
        }

        const uint32_t bo = (uint32_t)(c & 1) * ATILE;
        const uint32_t aAddr = aBase + bo;
        const uint32_t bAddr = bBase + bo;

        #pragma unroll
        for (int ks = 0; ks < 4; ++ks) {
            uint32_t af[4][4];
            #pragma unroll
            for (int mt = 0; mt < 4; ++mt)
                ldm_x4(af[mt], aAddr + mt*16*LDT + ks*32);

            uint32_t bf[4][2];
            {
                uint32_t r[4];
                ldm_x4(r, bAddr + ks*32);
                bf[0][0] = r[0]; bf[0][1] = r[2];
                bf[1][0] = r[1]; bf[1][1] = r[3];
                ldm_x4(r, bAddr + 16*LDT + ks*32);
                bf[2][0] = r[0]; bf[2][1] = r[2];
                bf[3][0] = r[1]; bf[3][1] = r[3];
            }
            #pragma unroll
            for (int mt = 0; mt < 4; ++mt)
                #pragma unroll
                for (int nt = 0; nt < 4; ++nt)
                    mma_f16(acc[mt][nt], af[mt], bf[nt]);
        }
    }
}

// ---- batched QKV projection
__global__ void __launch_bounds__(256, 2) qkv_gemm_kernel(
    const __half* __restrict__ AB, const __half* __restrict__ WB,
    const float* __restrict__ bq, const float* __restrict__ bk,
    const float* __restrict__ bv,
    __half* __restrict__ qh, __half* __restrict__ kh, __half* __restrict__ vth)
{
    extern __shared__ char smem[];
    const int z   = blockIdx.z;
    const int tid = threadIdx.x;
    const int bm  = blockIdx.y * 128;
    const int bn  = blockIdx.x * 128;

    const __half* A = AB + (size_t)z * NM * ND;
    const __half* W = WB + (size_t)z * ND * ND;
    const float* bias = (z == 0) ? bq : (z == 1) ? bk : bv;
    const float scale = (z == 0) ? QSCALE : 1.0f;

    float acc[4][4][4];
    gemm_mainloop(A, W, smem, tid, bm, bn, acc);

    const int lane = tid & 31;
    const int wid  = tid >> 5;
    const int wm   = wid >> 2;
    const int wn   = wid & 3;
    const int g  = lane >> 2;
    const int cj = (lane & 3) * 2;
    #pragma unroll
    for (int mt = 0; mt < 4; ++mt) {
        #pragma unroll
        for (int nt = 0; nt < 4; ++nt) {
            const int n  = bn + wn*32 + nt*8 + cj;
            const float bx = bias[n], by = bias[n+1];
            #pragma unroll
            for (int half_ = 0; half_ < 2; ++half_) {
                const int m = bm + wm*64 + mt*16 + g + half_*8;
                const float vx = (acc[mt][nt][half_*2+0] + bx) * scale;
                const float vy = (acc[mt][nt][half_*2+1] + by) * scale;
                const int b_ = m >> 11, s_ = m & (NS-1);
                const int h_ = n >> 6,  d_ = n & 63;
                if (z < 2) {
                    __half* OH = (z == 0) ? qh : kh;
                    const size_t idx = ((size_t)(b_*NH + h_) << 17) + ((size_t)s_ << 6) + d_;
                    *(uint32_t*)&OH[idx] = f22h2(vx, vy);
                } else {
                    const size_t idx = ((size_t)(b_*NH + h_) << 17) + ((size_t)d_ << 11) + s_;
                    vth[idx] = __float2half_rn(vx);
                    vth[idx + 2048] = __float2half_rn(vy);
                }
            }
        }
    }
}

// ---- O projection: fp32 output
__global__ void __launch_bounds__(256, 2) oproj_gemm_kernel(
    const __half* __restrict__ A, const __half* __restrict__ W,
    const float* __restrict__ bias, float* __restrict__ C)
{
    extern __shared__ char smem[];
    const int tid = threadIdx.x;
    const int bm  = blockIdx.y * 128;
    const int bn  = blockIdx.x * 128;

    float acc[4][4][4];
    gemm_mainloop(A, W, smem, tid, bm, bn, acc);

    const int lane = tid & 31;
    const int wid  = tid >> 5;
    const int wm   = wid >> 2;
    const int wn   = wid & 3;
    const int g  = lane >> 2;
    const int cj = (lane & 3) * 2;
    #pragma unroll
    for (int mt = 0; mt < 4; ++mt) {
        #pragma unroll
        for (int nt = 0; nt < 4; ++nt) {
            const int n  = bn + wn*32 + nt*8 + cj;
            const float bx = bias[n], by = bias[n+1];
            #pragma unroll
            for (int half_ = 0; half_ < 2; ++half_) {
                const int m = bm + wm*64 + mt*16 + g + half_*8;
                float2 v;
                v.x = acc[mt][nt][half_*2+0] + bx;
                v.y = acc[mt][nt][half_*2+1] + by;
                *(float2*)&C[(size_t)m * ND + n] = v;
            }
        }
    }
}

// ============================================================================
// flash attention (R15 arithmetic, triple-buffered K/V stages).
// CTA: 128 q-rows, 8 warps, occ 2. ex2.approx.f32 softmax, no online max.
// ============================================================================
#define QT  128
#define SST (QT*LDT)              // 18432 (Q region)
#define OKH 0
#define OVH (64*LDT)              // 9216
#define STG (2*64*LDT)            // 18432 per stage
#define NT  (NS/64)               // 32 stages
#define SMEM_ATTN (SST + 3*STG)   // 73728

__device__ __forceinline__ void attn_load_stage(
    uint32_t s0, int t, int tid, size_t base,
    const __half* Kh, const __half* Vh)
{
    #pragma unroll
    for (int p = 0; p < 2; ++p) {
        const int idx = tid + p*256;
        const int row = idx >> 3;
        const int c   = idx & 7;
        const size_t gk = base + (size_t)(t*64 + row)*64 + c*8;
        const size_t gv = base + (size_t)row*2048 + (size_t)t*64 + c*8;
        const uint32_t d = (uint32_t)row*LDT + (uint32_t)c*16;
        cp_async16(s0 + OKH + d, Kh + gk);
        cp_async16(s0 + OVH + d, Vh + gv);
    }
}

__global__ void __launch_bounds__(256, 2) attn_mma_kernel(
    const __half* __restrict__ Qh,
    const __half* __restrict__ Kh, const __half* __restrict__ Vh,
    __half* __restrict__ O)
{
    extern __shared__ char smem[];
    const uint32_t sb = smem_u32(smem);
    const int tid  = threadIdx.x;
    const int lane = tid & 31;
    const int w    = tid >> 5;
    const int hh   = blockIdx.y, bb = blockIdx.z;
    const int q0   = blockIdx.x * QT;
    const size_t base = ((size_t)(bb*NH + hh)) << 17;

    // Q tile + stage 0 (group 0), stage 1 (group 1)
    {
        #pragma unroll
        for (int p = 0; p < 4; ++p) {
            const int idx = tid + p*256;
            const int row = idx >> 3;
            const int c   = idx & 7;
            const size_t gq = base + (size_t)(q0 + row)*64 + c*8;
            cp_async16(sb + (uint32_t)row*LDT + (uint32_t)c*16, Qh + gq);
        }
    }
    attn_load_stage(sb + SST + 0*STG, 0, tid, base, Kh, Vh);
    cp_commit();                                  // g0: Q + stage0
    attn_load_stage(sb + SST + 1*STG, 1, tid, base, Kh, Vh);
    cp_commit();                                  // g1: stage1

    float o[8][4];
    #pragma unroll
    for (int nt = 0; nt < 8; ++nt)
        #pragma unroll
        for (int j = 0; j < 4; ++j) o[nt][j] = 0.f;
    float lrow[2] = {0.f, 0.f};

    const uint32_t lrm = lane & 15;
    const uint32_t lkb = (lane >> 4) * 16;
    const uint32_t aH = sb + (w*16 + lrm)*LDT + lkb;

    // rotating stage offsets: cur = t%3
    uint32_t bufs[3] = {sb + SST, sb + SST + STG, sb + SST + 2*STG};
    int cur = 0;

    for (int t = 0; t < NT; ++t) {
        cp_wait_1();            // this thread's stage-t copies complete
        __syncthreads();        // all threads' stage-t done; all done compute t-1

        // prefetch stage t+2 into the buffer freed by compute t-1
        if (t + 2 < NT) {
            const int nb = (cur + 2 >= 3) ? cur - 1 : cur + 2;
            attn_load_stage(bufs[nb], t + 2, tid, base, Kh, Vh);
        }
        cp_commit();            // uniform group counting (empty at tail)

        const uint32_t st = bufs[cur];
        const uint32_t bK = st + OKH + lrm*LDT + lkb;
        const uint32_t bV = st + OVH + lrm*LDT + lkb;

        // ---- S2 = Qh . Kh^T (log2-domain scores)
        float s[8][4];
        #pragma unroll
        for (int nt = 0; nt < 8; ++nt)
            #pragma unroll
            for (int j = 0; j < 4; ++j) s[nt][j] = 0.f;

        #pragma unroll
        for (int ks = 0; ks < 4; ++ks) {
            uint32_t ah[4], bf[8][2];
            ldm_x4(ah, aH + ks*32);
            #pragma unroll
            for (int pr = 0; pr < 4; ++pr) {
                uint32_t r[4];
                ldm_x4(r, bK + pr*16*LDT + ks*32);
                bf[2*pr][0]   = r[0]; bf[2*pr][1]   = r[2];
                bf[2*pr+1][0] = r[1]; bf[2*pr+1][1] = r[3];
            }
            #pragma unroll
            for (int nt = 0; nt < 8; ++nt)
                mma_f16(s[nt], ah, bf[nt]);
        }

        // ---- P = 2^s, accumulate l (fp32 MUFU, warp shuffles)
        uint32_t ph[4][4];
        #pragma unroll
        for (int rh = 0; rh < 2; ++rh) {
            float rs = 0.f;
            #pragma unroll
            for (int nt = 0; nt < 8; ++nt) {
                const float e0 = ex2f(s[nt][2*rh]);
                const float e1 = ex2f(s[nt][2*rh+1]);
                rs += e0 + e1;
                ph[nt>>1][(nt&1)*2 + rh] = f22h2(e0, e1);
            }
            rs += __shfl_xor_sync(0xffffffffu, rs, 1);
            rs += __shfl_xor_sync(0xffffffffu, rs, 2);
            lrow[rh] += rs;
        }

        // ---- O += Ph . Vh
        #pragma unroll
        for (int ks = 0; ks < 4; ++ks) {
            uint32_t bv[8][2];
            #pragma unroll
            for (int pr = 0; pr < 4; ++pr) {
                uint32_t r[4];
                ldm_x4(r, bV + pr*16*LDT + ks*32);
                bv[2*pr][0]   = r[0]; bv[2*pr][1]   = r[2];
                bv[2*pr+1][0] = r[1]; bv[2*pr+1][1] = r[3];
            }
            #pragma unroll
            for (int nt = 0; nt < 8; ++nt)
                mma_f16(o[nt], ph[ks], bv[nt]);
        }

        cur = (cur + 1 == 3) ? 0 : cur + 1;
    }

    // ---- epilogue: normalize, write fp16 activations (stride 1024)
    const int g  = lane >> 2;
    const int cq = (lane & 3) * 2;
    #pragma unroll
    for (int rh = 0; rh < 2; ++rh) {
        const float inv = 1.f / lrow[rh];
        const int qrow = q0 + w*16 + g + rh*8;
        __half* Orow = O + ((size_t)bb*NS + qrow) * ND;
        #pragma unroll
        for (int nt = 0; nt < 8; ++nt) {
            const float vx = o[nt][2*rh]   * inv;
            const float vy = o[nt][2*rh+1] * inv;
            const int colD = hh*64 + nt*8 + cq;
            *(uint32_t*)&Orow[colD] = f22h2(vx, vy);
        }
    }
}

// ---------------- launch ----------------
extern "C" void kernel_launch(void* const* d_in, const int* in_sizes, int n_in,
                              void* d_out, int out_size)
{
    const float* Q  = (const float*)d_in[0];
    const float* K  = (const float*)d_in[1];
    const float* V  = (const float*)d_in[2];
    const float* Wq = (const float*)d_in[3];
    const float* bq = (const float*)d_in[4];
    const float* Wk = (const float*)d_in[5];
    const float* bk = (const float*)d_in[6];
    const float* Wv = (const float*)d_in[7];
    const float* bv = (const float*)d_in[8];
    const float* Wo = (const float*)d_in[9];
    const float* bo = (const float*)d_in[10];
    float* out = (float*)d_out;

    void *pab, *pwb, *pqh, *pkh, *pvh;
    cudaGetSymbolAddress(&pab, g_abuf);
    cudaGetSymbolAddress(&pwb, g_wbuf);
    cudaGetSymbolAddress(&pqh, g_qh);
    cudaGetSymbolAddress(&pkh, g_kh);
    cudaGetSymbolAddress(&pvh, g_vth);
    __half* ab = (__half*)pab;
    __half* wb = (__half*)pwb;

    cudaFuncSetAttribute((const void*)qkv_gemm_kernel,
                         cudaFuncAttributeMaxDynamicSharedMemorySize, SMEM_GEMM);
    cudaFuncSetAttribute((const void*)oproj_gemm_kernel,
                         cudaFuncAttributeMaxDynamicSharedMemorySize, SMEM_GEMM);
    cudaFuncSetAttribute((const void*)attn_mma_kernel,
                         cudaFuncAttributeMaxDynamicSharedMemorySize, SMEM_ATTN);

    // 1) merged converts (activations + weights, one launch)
    conv_kernel<<<ACT_BLKS + W_BLKS, 256>>>(Q, K, V, Wq, Wk, Wv, Wo, ab, wb);

    // 2) batched QKV projections (Q scaled by 0.125*log2e)
    qkv_gemm_kernel<<<dim3(ND/128, NM/128, 3), 256, SMEM_GEMM>>>(
        ab, wb, bq, bk, bv,
        (__half*)pqh, (__half*)pkh, (__half*)pvh);

    // 3) attention -> fp16 activations into g_abuf section 0
    attn_mma_kernel<<<dim3(NS/QT, NH, NB), 256, SMEM_ATTN>>>(
        (const __half*)pqh, (const __half*)pkh, (const __half*)pvh, ab);

    // 4) output projection (Wo is section 3 of g_wbuf)
    oproj_gemm_kernel<<<dim3(ND/128, NM/128), 256, SMEM_GEMM>>>(
        ab, wb + (size_t)3*ND*ND, bo, out);
}